// round 4
// baseline (speedup 1.0000x reference)
#include <cuda_runtime.h>
#include <cuda_bf16.h>
#include <cstdint>

#define N_NODES 100000
#define D 32

// 12.8 MB scratch for the aggregation result (allocation-free per harness rules)
__device__ float g_agg[N_NODES * D];

// ---------------------------------------------------------------------------
// Scatter: one warp per edge (grid-stride over edges). Lane c gathers
// x[src][c] (coalesced 128B row) and atomicAdds into agg[dst][c]
// (consecutive addresses -> RED to L2, no return).
// edge_index arrives as int32 (harness dtype set is f32/i32/bf16).
// ---------------------------------------------------------------------------
__global__ void scatter_kernel(const float* __restrict__ x,
                               const int* __restrict__ edge_index,
                               float* __restrict__ agg,
                               int n_edges) {
    int lane = threadIdx.x & 31;
    int warp0 = (blockIdx.x * blockDim.x + threadIdx.x) >> 5;
    int warp_stride = (gridDim.x * blockDim.x) >> 5;

    for (int e = warp0; e < n_edges; e += warp_stride) {
        int src = __ldg(&edge_index[e]);            // row 0: src
        int dst = __ldg(&edge_index[n_edges + e]);  // row 1: dst

        float v = __ldg(&x[(size_t)src * D + lane]);
        atomicAdd(&agg[(size_t)dst * D + lane], v);
    }
}

// ---------------------------------------------------------------------------
// GEMM: out = agg @ W^T.  W is [D_OUT, D_IN] = [32, 32].
// Block = 1024 threads = 32 nodes x 32 output features.
// Shared tiles padded to stride 33 for bank-conflict-free access.
// ---------------------------------------------------------------------------
__global__ void gemm_kernel(const float* __restrict__ agg,
                            const float* __restrict__ W,
                            float* __restrict__ out,
                            int n_nodes) {
    __shared__ float Ws[D * 33];   // Ws[j*33 + k] = W[j][k]
    __shared__ float As[D * 33];   // As[i*33 + k] = agg[node_base + i][k]

    int tid = threadIdx.x;          // 0..1023
    int i = tid >> 5;               // node within tile  (0..31)
    int j = tid & 31;               // output feature    (0..31)

    // Load W (1024 floats) coalesced, scatter into padded layout
    {
        int r = tid >> 5, c = tid & 31;
        Ws[r * 33 + c] = W[r * D + c];
    }

    int node_base = blockIdx.x * D;  // 32 nodes per block

    // Load agg tile coalesced
    {
        int r = tid >> 5, c = tid & 31;
        int node = node_base + r;
        As[r * 33 + c] = (node < n_nodes) ? agg[node * D + c] : 0.0f;
    }
    __syncthreads();

    int node = node_base + i;
    if (node < n_nodes) {
        float acc = 0.0f;
#pragma unroll
        for (int k = 0; k < D; ++k) {
            // As[i*33+k]: same address for all j in this i-group -> broadcast
            // Ws[j*33+k]: bank (j+k)%32 distinct across lanes -> conflict-free
            acc += As[i * 33 + k] * Ws[j * 33 + k];
        }
        out[node * D + j] = acc;
    }
}

// ---------------------------------------------------------------------------
extern "C" void kernel_launch(void* const* d_in, const int* in_sizes, int n_in,
                              void* d_out, int out_size) {
    const float* x = (const float*)d_in[0];
    const int* edge_index = (const int*)d_in[1];
    const float* W = (const float*)d_in[2];
    float* out = (float*)d_out;

    int n_edges = in_sizes[1] / 2;
    int n_nodes = in_sizes[0] / D;

    float* agg;
    cudaGetSymbolAddress((void**)&agg, g_agg);

    // 1) zero the aggregation buffer (async memset is graph-capturable)
    cudaMemsetAsync(agg, 0, (size_t)N_NODES * D * sizeof(float));

    // 2) scatter-add: one warp per edge, 8 warps (256 threads) per block,
    //    grid-stride so each warp handles ~several edges back-to-back.
    {
        int threads = 256;                 // 8 warps
        int blocks = 12800;                // ~86 blocks/SM worth of waves; grid-stride
        scatter_kernel<<<blocks, threads>>>(x, edge_index, agg, n_edges);
    }

    // 3) GEMM: 32 nodes per block
    {
        int blocks = (n_nodes + D - 1) / D;
        gemm_kernel<<<blocks, 1024>>>(agg, W, out, n_nodes);
    }
}